// round 1
// baseline (speedup 1.0000x reference)
#include <cuda_runtime.h>
#include <cuda_bf16.h>

#define D 128
#define DV 32            // D / 4 float4 per row

// Table sizes (floats)
#define SZ_ATOM  (46 * D)   // 5888
#define SZ_DEG   (6  * D)   // 768
#define SZ_CHG   (11 * D)   // 1408
#define SZ_HYB   (3  * D)   // 384
#define SZ_H     (5  * D)   // 640
#define SZ_CHI   (4  * D)   // 512
#define SZ_BOND  (5  * D)   // 640
#define SZ_W     (7  * D)   // 896
#define SZ_B     (D)        // 128

#define OFF_ATOM 0
#define OFF_DEG  (OFF_ATOM + SZ_ATOM)
#define OFF_CHG  (OFF_DEG  + SZ_DEG)
#define OFF_HYB  (OFF_CHG  + SZ_CHG)
#define OFF_H    (OFF_HYB  + SZ_HYB)
#define OFF_CHI  (OFF_H    + SZ_H)
#define OFF_BOND (OFF_CHI  + SZ_CHI)
#define OFF_W    (OFF_BOND + SZ_BOND)
#define OFF_B    (OFF_W    + SZ_W)
#define SMEM_FLOATS (OFF_B + SZ_B)   // 11264 floats = 45056 B

__device__ __forceinline__ void add4(float4& a, const float4 b) {
    a.x += b.x; a.y += b.y; a.z += b.z; a.w += b.w;
}
__device__ __forceinline__ void fma4(float4& a, float s, const float4 b) {
    a.x = fmaf(s, b.x, a.x); a.y = fmaf(s, b.y, a.y);
    a.z = fmaf(s, b.z, a.z); a.w = fmaf(s, b.w, a.w);
}

__global__ void __launch_bounds__(256)
atom_featurizer_kernel(
    const int* __restrict__ atom_idx,
    const int* __restrict__ degree_idx,
    const int* __restrict__ charge_idx,
    const int* __restrict__ hybrid_idx,
    const int* __restrict__ numh_idx,
    const int* __restrict__ chiral_idx,
    const int* __restrict__ bond_counts,   // [N,4]
    const float* __restrict__ scalar3,     // [N,3]
    const float* __restrict__ E_atom,
    const float* __restrict__ E_deg,
    const float* __restrict__ E_chg,
    const float* __restrict__ E_hyb,
    const float* __restrict__ E_h,
    const float* __restrict__ E_chi,
    const float* __restrict__ E_bond,
    const float* __restrict__ Wm,
    const float* __restrict__ bv,
    float* __restrict__ out,
    int n)
{
    __shared__ float s[SMEM_FLOATS];

    // Cooperative table staging
    const int t = threadIdx.x;
    for (int i = t; i < SZ_ATOM; i += 256) s[OFF_ATOM + i] = E_atom[i];
    for (int i = t; i < SZ_DEG;  i += 256) s[OFF_DEG  + i] = E_deg[i];
    for (int i = t; i < SZ_CHG;  i += 256) s[OFF_CHG  + i] = E_chg[i];
    for (int i = t; i < SZ_HYB;  i += 256) s[OFF_HYB  + i] = E_hyb[i];
    for (int i = t; i < SZ_H;    i += 256) s[OFF_H    + i] = E_h[i];
    for (int i = t; i < SZ_CHI;  i += 256) s[OFF_CHI  + i] = E_chi[i];
    for (int i = t; i < SZ_BOND; i += 256) s[OFF_BOND + i] = E_bond[i];
    for (int i = t; i < SZ_W;    i += 256) s[OFF_W    + i] = Wm[i];
    for (int i = t; i < SZ_B;    i += 256) s[OFF_B    + i] = bv[i];
    __syncthreads();

    const float4* s4 = reinterpret_cast<const float4*>(s);
    const int lane = t & 31;
    const int warp_global = (blockIdx.x * 256 + t) >> 5;
    const int nwarps = (gridDim.x * 256) >> 5;

    for (int i = warp_global; i < n; i += nwarps) {
        // scalar per-atom metadata (same address across lanes -> broadcast)
        const int ai = atom_idx[i];
        const int di = degree_idx[i];
        const int ci = charge_idx[i];
        const int hi = hybrid_idx[i];
        const int ni = numh_idx[i];
        const int xi = chiral_idx[i];
        const int4 bc = reinterpret_cast<const int4*>(bond_counts)[i];
        const float s0 = scalar3[3 * i + 0];
        const float s1 = scalar3[3 * i + 1];
        const float s2 = scalar3[3 * i + 2];

        // acc = b + six categorical gathers (each row: 32 float4, lane-indexed)
        float4 acc = s4[(OFF_B >> 2) + lane];
        add4(acc, s4[(OFF_ATOM >> 2) + ai * DV + lane]);
        add4(acc, s4[(OFF_DEG  >> 2) + di * DV + lane]);
        add4(acc, s4[(OFF_CHG  >> 2) + ci * DV + lane]);
        add4(acc, s4[(OFF_HYB  >> 2) + hi * DV + lane]);
        add4(acc, s4[(OFF_H    >> 2) + ni * DV + lane]);
        add4(acc, s4[(OFF_CHI  >> 2) + xi * DV + lane]);

        // bond-context rows (masked) + linear W terms
        const int c0 = bc.x, c1 = bc.y, c2 = bc.z, c3 = bc.w;
        if (c0 > 0) add4(acc, s4[(OFF_BOND >> 2) + c0 * DV + lane]);
        if (c1 > 0) add4(acc, s4[(OFF_BOND >> 2) + c1 * DV + lane]);
        if (c2 > 0) add4(acc, s4[(OFF_BOND >> 2) + c2 * DV + lane]);
        if (c3 > 0) add4(acc, s4[(OFF_BOND >> 2) + c3 * DV + lane]);

        fma4(acc, s0,          s4[(OFF_W >> 2) + 0 * DV + lane]);
        fma4(acc, s1,          s4[(OFF_W >> 2) + 1 * DV + lane]);
        fma4(acc, s2,          s4[(OFF_W >> 2) + 2 * DV + lane]);
        fma4(acc, c0 * 0.25f,  s4[(OFF_W >> 2) + 3 * DV + lane]);
        fma4(acc, c1 * 0.25f,  s4[(OFF_W >> 2) + 4 * DV + lane]);
        fma4(acc, c2 * 0.25f,  s4[(OFF_W >> 2) + 5 * DV + lane]);
        fma4(acc, c3 * 0.25f,  s4[(OFF_W >> 2) + 6 * DV + lane]);

        reinterpret_cast<float4*>(out)[(long long)i * DV + lane] = acc;
    }
}

extern "C" void kernel_launch(void* const* d_in, const int* in_sizes, int n_in,
                              void* d_out, int out_size) {
    const int*   atom_idx    = (const int*)d_in[0];
    const int*   degree_idx  = (const int*)d_in[1];
    const int*   charge_idx  = (const int*)d_in[2];
    const int*   hybrid_idx  = (const int*)d_in[3];
    const int*   numh_idx    = (const int*)d_in[4];
    const int*   chiral_idx  = (const int*)d_in[5];
    const int*   bond_counts = (const int*)d_in[6];
    const float* scalar3     = (const float*)d_in[7];
    const float* E_atom      = (const float*)d_in[8];
    const float* E_deg       = (const float*)d_in[9];
    const float* E_chg       = (const float*)d_in[10];
    const float* E_hyb       = (const float*)d_in[11];
    const float* E_h         = (const float*)d_in[12];
    const float* E_chi       = (const float*)d_in[13];
    const float* E_bond      = (const float*)d_in[14];
    const float* Wm          = (const float*)d_in[15];
    const float* bv          = (const float*)d_in[16];
    float* out = (float*)d_out;

    const int n = in_sizes[0];
    const int blocks = 148 * 4;   // grid-stride; ~5 CTAs/SM smem-limited
    atom_featurizer_kernel<<<blocks, 256>>>(
        atom_idx, degree_idx, charge_idx, hybrid_idx, numh_idx, chiral_idx,
        bond_counts, scalar3, E_atom, E_deg, E_chg, E_hyb, E_h, E_chi,
        E_bond, Wm, bv, out, n);
}